// round 15
// baseline (speedup 1.0000x reference)
#include <cuda_runtime.h>
#include <cuda_fp16.h>
#include <math.h>
#include <cstdint>

#define B_  8
#define T_  2048
#define E_  1024
#define H_  128
#define BT_ (B_*T_)

// scratch (allocation-free: __device__ globals)
__device__ float g_q[BT_*H_];
__device__ float g_k[BT_*H_];
__device__ float g_v[BT_*H_];
__device__ __half g_w1[3*H_*E_], g_w2[3*H_*E_];   // W^T split: [3][128 n][1024 k]

// ---------------------------------------------------------------------------
__device__ __forceinline__ uint32_t smem_u32(const void* p) {
    uint32_t a;
    asm("{ .reg .u64 t; cvta.to.shared.u64 t, %1; cvt.u32.u64 %0, t; }"
        : "=r"(a) : "l"(p));
    return a;
}

__device__ __forceinline__ void split2(float x, float y, uint32_t& hi, uint32_t& lo) {
    __half2 h = __floats2half2_rn(x, y);
    float2 f = __half22float2(h);
    __half2 l = __floats2half2_rn(x - f.x, y - f.y);
    hi = *(uint32_t*)&h; lo = *(uint32_t*)&l;
}

__device__ __forceinline__ void mma16(float* d, const uint32_t* a, const uint32_t* b) {
    asm volatile(
        "mma.sync.aligned.m16n8k16.row.col.f32.f16.f16.f32 "
        "{%0,%1,%2,%3}, {%4,%5,%6,%7}, {%8,%9}, {%0,%1,%2,%3};"
        : "+f"(d[0]), "+f"(d[1]), "+f"(d[2]), "+f"(d[3])
        : "r"(a[0]), "r"(a[1]), "r"(a[2]), "r"(a[3]), "r"(b[0]), "r"(b[1]));
}

__device__ __forceinline__ void ldsm4(uint32_t* r, uint32_t addr) {
    asm volatile("ldmatrix.sync.aligned.m8n8.x4.shared.b16 {%0,%1,%2,%3}, [%4];"
        : "=r"(r[0]), "=r"(r[1]), "=r"(r[2]), "=r"(r[3]) : "r"(addr));
}
__device__ __forceinline__ void ldsm4t(uint32_t* r, uint32_t addr) {
    asm volatile("ldmatrix.sync.aligned.m8n8.x4.trans.shared.b16 {%0,%1,%2,%3}, [%4];"
        : "=r"(r[0]), "=r"(r[1]), "=r"(r[2]), "=r"(r[3]) : "r"(addr));
}

// ---------------------------------------------------------------------------
// W -> W^T, split to fp16 halves.  grid (E/32, H/32, 3), 256 thr
// ---------------------------------------------------------------------------
__global__ void prep_w(const float* __restrict__ Wq,
                       const float* __restrict__ Wk,
                       const float* __restrict__ Wv)
{
    __shared__ float tile[32][33];
    const int sel = blockIdx.z;
    const float* __restrict__ W = (sel == 0) ? Wq : (sel == 1) ? Wk : Wv;
    const int k0 = blockIdx.x * 32, n0 = blockIdx.y * 32;
    const int tx = threadIdx.x & 31, ty = threadIdx.x >> 5;
#pragma unroll
    for (int i = 0; i < 4; i++)
        tile[ty + 8*i][tx] = W[(size_t)(k0 + ty + 8*i) * H_ + n0 + tx];
    __syncthreads();
    uint32_t* w1 = (uint32_t*)g_w1;
    uint32_t* w2 = (uint32_t*)g_w2;
#pragma unroll
    for (int r = 0; r < 2; r++) {
        int slot = r * 256 + threadIdx.x;
        int ni = slot >> 4, kp = slot & 15;
        float a = tile[2*kp][ni], b = tile[2*kp + 1][ni];
        uint32_t h, l;
        split2(a, b, h, l);
        size_t o = ((size_t)(sel * H_ + n0 + ni) * E_ + k0 + 2*kp) >> 1;
        w1[o] = h; w2[o] = l;
    }
}

// ---------------------------------------------------------------------------
// Projection: out = x @ W  via mma.sync fp16 split (3 products; 2 for V).
// CTA 64x128, 8 warps (2m x 4n), warp tile 32x32. K chunks of 32.
// ldmatrix fragments; double-buffered smem (1 sync per chunk); LDG prefetch.
// ---------------------------------------------------------------------------
#define PJS 40                       // halves per smem row
#define PJ_BUFH 15360                // halves per buffer
#define PJ_A1 0
#define PJ_A2 2560
#define PJ_B1 5120
#define PJ_B2 10240
#define PJ_SMEM (2 * PJ_BUFH * 2)    // 61440 B

__global__ __launch_bounds__(256, 2) void proj_tc(const float* __restrict__ x)
{
    extern __shared__ __half sh[];
    const uint32_t sb = smem_u32(sh);
    const int t    = threadIdx.x;
    const int wid  = t >> 5, lane = t & 31;
    const int wm   = wid >> 2, wn = wid & 3;
    const int g    = lane >> 2, tg = lane & 3;
    const int sel  = blockIdx.y;
    const int m0   = blockIdx.x * 64;

    const uint4* __restrict__ ws1 = (const uint4*)(g_w1 + (size_t)sel * H_ * E_);
    const uint4* __restrict__ ws2 = (const uint4*)(g_w2 + (size_t)sel * H_ * E_);
    float* outp = (sel == 0) ? g_q : (sel == 1) ? g_k : g_v;

    const int aoff = (lane & 15) * PJS + 8 * (lane >> 4);
    const int boff = ((lane & 7) + 8 * (lane >> 4)) * PJS + 8 * ((lane >> 3) & 1);

    float acc[2][4][4];
#pragma unroll
    for (int mi = 0; mi < 2; mi++)
#pragma unroll
        for (int ni = 0; ni < 4; ni++)
#pragma unroll
            for (int r = 0; r < 4; r++) acc[mi][ni][r] = 0.f;

    const int ac4 = t & 7;
    const int bc8 = t & 3;
    float4 fa[2];
    uint4  pw1[2], pw2[2];

    auto fetch = [&](int c) {
        const int k0 = c * 32;
#pragma unroll
        for (int p = 0; p < 2; p++) {
            int row = (p * 256 + t) >> 3;
            fa[p] = *(const float4*)&x[(size_t)(m0 + row) * E_ + k0 + ac4 * 4];
        }
#pragma unroll
        for (int p = 0; p < 2; p++) {
            int row = (p * 256 + t) >> 2;
            size_t off = ((size_t)row * E_ + k0) / 8 + bc8;
            pw1[p] = ws1[off];
            pw2[p] = ws2[off];
        }
    };
    auto store = [&](int buf) {
        __half* dst = sh + buf * PJ_BUFH;
#pragma unroll
        for (int p = 0; p < 2; p++) {
            int row = (p * 256 + t) >> 3;
            float4 v = fa[p];
            uint32_t h0, l0, h1, l1;
            split2(v.x, v.y, h0, l0);
            split2(v.z, v.w, h1, l1);
            int o = row * PJS + ac4 * 4;
            *(uint32_t*)&dst[PJ_A1 + o]     = h0;
            *(uint32_t*)&dst[PJ_A1 + o + 2] = h1;
            *(uint32_t*)&dst[PJ_A2 + o]     = l0;
            *(uint32_t*)&dst[PJ_A2 + o + 2] = l1;
        }
#pragma unroll
        for (int p = 0; p < 2; p++) {
            int row = (p * 256 + t) >> 2;
            int o = row * PJS + bc8 * 8;
            *(uint4*)&dst[PJ_B1 + o] = pw1[p];
            *(uint4*)&dst[PJ_B2 + o] = pw2[p];
        }
    };

    fetch(0);
    store(0);
    __syncthreads();

    for (int c = 0; c < 32; c++) {
        const int p = c & 1;
        if (c < 31) fetch(c + 1);

        const uint32_t bufb = sb + 2 * (p * PJ_BUFH);
        const uint32_t a1b = bufb + 2 * (PJ_A1 + wm * 32 * PJS + aoff);
        const uint32_t a2b = bufb + 2 * (PJ_A2 + wm * 32 * PJS + aoff);
        const uint32_t b1b = bufb + 2 * (PJ_B1 + wn * 32 * PJS + boff);
        const uint32_t b2b = bufb + 2 * (PJ_B2 + wn * 32 * PJS + boff);

#pragma unroll
        for (int s = 0; s < 2; s++) {
            uint32_t a1[2][4], a2[2][4];
#pragma unroll
            for (int mi = 0; mi < 2; mi++) {
                ldsm4(a1[mi], a1b + 2 * (mi * 16 * PJS + s * 16));
                ldsm4(a2[mi], a2b + 2 * (mi * 16 * PJS + s * 16));
            }
#pragma unroll
            for (int ng = 0; ng < 2; ng++) {
                uint32_t b1[4], b2[4];
                ldsm4(b1, b1b + 2 * (ng * 16 * PJS + s * 16));
                ldsm4(b2, b2b + 2 * (ng * 16 * PJS + s * 16));
#pragma unroll
                for (int mi = 0; mi < 2; mi++) {
                    mma16(acc[mi][2*ng],     a1[mi], b1);
                    mma16(acc[mi][2*ng + 1], a1[mi], b1 + 2);
                    mma16(acc[mi][2*ng],     a1[mi], b2);
                    mma16(acc[mi][2*ng + 1], a1[mi], b2 + 2);
                    if (sel < 2) {
                        mma16(acc[mi][2*ng],     a2[mi], b1);
                        mma16(acc[mi][2*ng + 1], a2[mi], b1 + 2);
                    }
                }
            }
        }
        if (c < 31) {
            store(p ^ 1);
            __syncthreads();
        }
    }

#pragma unroll
    for (int mi = 0; mi < 2; mi++) {
        int row = m0 + wm * 32 + mi * 16 + g;
#pragma unroll
        for (int ni = 0; ni < 4; ni++) {
            int col = wn * 32 + ni * 8 + tg * 2;
            *(float2*)&outp[(size_t)row * H_ + col] =
                make_float2(acc[mi][ni][0], acc[mi][ni][1]);
            *(float2*)&outp[(size_t)(row + 8) * H_ + col] =
                make_float2(acc[mi][ni][2], acc[mi][ni][3]);
        }
    }
}

// ---------------------------------------------------------------------------
// Flash attention, FA2 register dataflow. BQ=64, BK=64. 4 warps x 16 rows,
// each warp owns full 64 S-cols and full 128 O-cols of its rows.
// Softmax fully warp-local (no smem exchange); P stays in registers.
// Q in registers; K/V single smem buffer; 128-thread CTA, 2 CTAs/SM.
// ---------------------------------------------------------------------------
#define KH1_ 0
#define KH2_ 8704
#define VS_  17408
#define A_SMEM ((3*64*136) * 2)   // 52224 B

__global__ __launch_bounds__(128, 2) void attn_tc(float* __restrict__ out)
{
    extern __shared__ __half shh[];
    const uint32_t sb = smem_u32(shh);

    const int t    = threadIdx.x;
    const int wid  = t >> 5, lane = t & 31;
    const int g    = lane >> 2, tg = lane & 3;
    const int qt   = (int)gridDim.x - 1 - (int)blockIdx.x;
    const int b    = blockIdx.y;
    const size_t base = (size_t)b * (T_ * H_);
    const float scale = 45.25483399593904f;   // sqrt(2048)

    // ldmatrix lane offsets (half indices)
    const int aoffQ = (lane & 15) * 136 + 8 * (lane >> 4);                          // A frag
    const int boffK = ((lane & 7) + 8 * (lane >> 4)) * 136 + 8 * ((lane >> 3) & 1); // B frag
    const int voffV = ((lane & 7) + 8 * ((lane >> 3) & 1)) * 136 + 8 * (lane >> 4); // B trans

    // ---- stage Q (64x128, scaled, split) into smem, then into registers ----
#pragma unroll
    for (int p = 0; p < 16; p++) {
        int idx = p * 128 + t;
        int row = idx >> 5, c4 = idx & 31;
        float4 v = *(const float4*)&g_q[base + (size_t)(qt * 64 + row) * H_ + c4 * 4];
        v.x *= scale; v.y *= scale; v.z *= scale; v.w *= scale;
        uint32_t h0, l0, h1, l1;
        split2(v.x, v.y, h0, l0);
        split2(v.z, v.w, h1, l1);
        int o = row * 136 + c4 * 4;
        *(uint32_t*)&shh[KH1_ + o]     = h0;
        *(uint32_t*)&shh[KH1_ + o + 2] = h1;
        *(uint32_t*)&shh[KH2_ + o]     = l0;
        *(uint32_t*)&shh[KH2_ + o + 2] = l1;
    }
    __syncthreads();

    uint32_t qa1[8][4], qa2[8][4];
    {
        const uint32_t qb1 = sb + 2 * (KH1_ + wid * 16 * 136 + aoffQ);
        const uint32_t qb2 = sb + 2 * (KH2_ + wid * 16 * 136 + aoffQ);
#pragma unroll
        for (int ks = 0; ks < 8; ks++) {
            ldsm4(qa1[ks], qb1 + 2 * (ks * 16));
            ldsm4(qa2[ks], qb2 + 2 * (ks * 16));
        }
    }

    float of[16][4];
#pragma unroll
    for (int nt = 0; nt < 16; nt++)
#pragma unroll
        for (int r = 0; r < 4; r++) of[nt][r] = 0.f;
    float mrun0 = -INFINITY, mrun1 = -INFINITY;
    float lrun0 = 0.f, lrun1 = 0.f;

    const int ntiles = qt + 1;
    const int krow = t >> 1;              // 0..63
    const int kcb  = (t & 1) * 16;        // float4 col base

    for (int kt = 0; kt < ntiles; kt++) {
        __syncthreads();   // prev tile consumed (and Q frags read on iter 0)
        // ---- K (split) + V (half) -> smem ----
#pragma unroll
        for (int pp = 0; pp < 16; pp++) {
            int c4 = kcb + pp;
            int o = krow * 136 + c4 * 4;
            float4 v = *(const float4*)&g_k[base + (size_t)(kt * 64 + krow) * H_ + c4 * 4];
            uint32_t h0, l0, h1, l1;
            split2(v.x, v.y, h0, l0);
            split2(v.z, v.w, h1, l1);
            *(uint32_t*)&shh[KH1_ + o]     = h0;
            *(uint32_t*)&shh[KH1_ + o + 2] = h1;
            *(uint32_t*)&shh[KH2_ + o]     = l0;
            *(uint32_t*)&shh[KH2_ + o + 2] = l1;
            float4 w = *(const float4*)&g_v[base + (size_t)(kt * 64 + krow) * H_ + c4 * 4];
            __half2 va = __floats2half2_rn(w.x, w.y);
            __half2 vb = __floats2half2_rn(w.z, w.w);
            uint2 u = make_uint2(*(uint32_t*)&va, *(uint32_t*)&vb);
            *(uint2*)&shh[VS_ + o] = u;
        }
        __syncthreads();

        // ---- S = Q K^T (16 rows x 64 cols per warp), split-2, 3 products ----
        float sf[8][4];
#pragma unroll
        for (int ni = 0; ni < 8; ni++)
#pragma unroll
            for (int r = 0; r < 4; r++) sf[ni][r] = 0.f;

        const uint32_t kb1b = sb + 2 * (KH1_ + boffK);
        const uint32_t kb2b = sb + 2 * (KH2_ + boffK);
#pragma unroll
        for (int ks = 0; ks < 8; ks++) {
#pragma unroll
            for (int ng = 0; ng < 4; ng++) {
                uint32_t kb1[4], kb2[4];
                ldsm4(kb1, kb1b + 2 * (ng * 16 * 136 + ks * 16));
                ldsm4(kb2, kb2b + 2 * (ng * 16 * 136 + ks * 16));
                mma16(sf[2*ng],     qa1[ks], kb1);
                mma16(sf[2*ng + 1], qa1[ks], kb1 + 2);
                mma16(sf[2*ng],     qa1[ks], kb2);
                mma16(sf[2*ng + 1], qa1[ks], kb2 + 2);
                mma16(sf[2*ng],     qa2[ks], kb1);
                mma16(sf[2*ng + 1], qa2[ks], kb1 + 2);
            }
        }

        // ---- causal mask on the diagonal tile ----
        const int row0 = wid * 16 + g;
        if (kt == qt) {
#pragma unroll
            for (int ni = 0; ni < 8; ni++) {
                int col = ni * 8 + tg * 2;
                if (col     > row0)     sf[ni][0] = -INFINITY;
                if (col + 1 > row0)     sf[ni][1] = -INFINITY;
                if (col     > row0 + 8) sf[ni][2] = -INFINITY;
                if (col + 1 > row0 + 8) sf[ni][3] = -INFINITY;
            }
        }

        // ---- warp-local online softmax ----
        float pm0 = -INFINITY, pm1 = -INFINITY;
#pragma unroll
        for (int ni = 0; ni < 8; ni++) {
            pm0 = fmaxf(pm0, fmaxf(sf[ni][0], sf[ni][1]));
            pm1 = fmaxf(pm1, fmaxf(sf[ni][2], sf[ni][3]));
        }
        pm0 = fmaxf(pm0, __shfl_xor_sync(0xffffffffu, pm0, 1));
        pm0 = fmaxf(pm0, __shfl_xor_sync(0xffffffffu, pm0, 2));
        pm1 = fmaxf(pm1, __shfl_xor_sync(0xffffffffu, pm1, 1));
        pm1 = fmaxf(pm1, __shfl_xor_sync(0xffffffffu, pm1, 2));

        float m0n = fmaxf(mrun0, pm0);
        float m1n = fmaxf(mrun1, pm1);
        float f0 = __expf(mrun0 - m0n);
        float f1 = __expf(mrun1 - m1n);
        mrun0 = m0n; mrun1 = m1n;

        float ps0 = 0.f, ps1 = 0.f;
        uint32_t pa[4][4];   // P A-fragments, built directly from S frags
#pragma unroll
        for (int kk = 0; kk < 4; kk++) {
            float e00 = __expf(sf[2*kk][0] - m0n);
            float e01 = __expf(sf[2*kk][1] - m0n);
            float e02 = __expf(sf[2*kk][2] - m1n);
            float e03 = __expf(sf[2*kk][3] - m1n);
            float e10 = __expf(sf[2*kk+1][0] - m0n);
            float e11 = __expf(sf[2*kk+1][1] - m0n);
            float e12 = __expf(sf[2*kk+1][2] - m1n);
            float e13 = __expf(sf[2*kk+1][3] - m1n);
            ps0 += e00 + e01 + e10 + e11;
            ps1 += e02 + e03 + e12 + e13;
            __half2 h;
            h = __floats2half2_rn(e00, e01); pa[kk][0] = *(uint32_t*)&h;
            h = __floats2half2_rn(e02, e03); pa[kk][1] = *(uint32_t*)&h;
            h = __floats2half2_rn(e10, e11); pa[kk][2] = *(uint32_t*)&h;
            h = __floats2half2_rn(e12, e13); pa[kk][3] = *(uint32_t*)&h;
        }
        ps0 += __shfl_xor_sync(0xffffffffu, ps0, 1);
        ps0 += __shfl_xor_sync(0xffffffffu, ps0, 2);
        ps1 += __shfl_xor_sync(0xffffffffu, ps1, 1);
        ps1 += __shfl_xor_sync(0xffffffffu, ps1, 2);
        lrun0 = lrun0 * f0 + ps0;
        lrun1 = lrun1 * f1 + ps1;

        // ---- rescale O ----
#pragma unroll
        for (int nt = 0; nt < 16; nt++) {
            of[nt][0] *= f0; of[nt][1] *= f0;
            of[nt][2] *= f1; of[nt][3] *= f1;
        }

        // ---- O += P V  (P in registers) ----
        const uint32_t vbb = sb + 2 * (VS_ + voffV);
#pragma unroll
        for (int kk = 0; kk < 4; kk++) {
#pragma unroll
            for (int ng = 0; ng < 8; ng++) {
                uint32_t vb[4];
                ldsm4t(vb, vbb + 2 * (kk * 16 * 136 + ng * 16));
                mma16(of[2*ng],     pa[kk], vb);
                mma16(of[2*ng + 1], pa[kk], vb + 2);
            }
        }
    }

    // ---- epilogue ----
    float inv0 = 1.f / lrun0;
    float inv1 = 1.f / lrun1;
    int grow = qt * 64 + wid * 16 + g;
#pragma unroll
    for (int nt = 0; nt < 16; nt++) {
        int col = nt * 8 + tg * 2;
        *(float2*)&out[base + (size_t)grow * H_ + col] =
            make_float2(of[nt][0] * inv0, of[nt][1] * inv0);
        *(float2*)&out[base + (size_t)(grow + 8) * H_ + col] =
            make_float2(of[nt][2] * inv1, of[nt][3] * inv1);
    }
}

// ---------------------------------------------------------------------------
extern "C" void kernel_launch(void* const* d_in, const int* in_sizes, int n_in,
                              void* d_out, int out_size)
{
    const float* x  = (const float*)d_in[0];
    const float* Wq = (const float*)d_in[1];
    const float* Wk = (const float*)d_in[2];
    const float* Wv = (const float*)d_in[3];
    float* out = (float*)d_out;

    prep_w<<<dim3(E_/32, H_/32, 3), 256>>>(Wq, Wk, Wv);

    cudaFuncSetAttribute(proj_tc,
                         cudaFuncAttributeMaxDynamicSharedMemorySize, PJ_SMEM);
    proj_tc<<<dim3(BT_/64, 3), 256, PJ_SMEM>>>(x);

    cudaFuncSetAttribute(attn_tc,
                         cudaFuncAttributeMaxDynamicSharedMemorySize, A_SMEM);
    attn_tc<<<dim3(T_/64, B_), 128, A_SMEM>>>(out);
}

// round 17
// speedup vs baseline: 1.5166x; 1.5166x over previous
#include <cuda_runtime.h>
#include <cuda_fp16.h>
#include <math.h>
#include <cstdint>

#define B_  8
#define T_  2048
#define E_  1024
#define H_  128
#define BT_ (B_*T_)

// scratch (allocation-free: __device__ globals)
__device__ float g_q[BT_*H_];
__device__ float g_k[BT_*H_];
__device__ float g_v[BT_*H_];
__device__ __half g_w1[3*H_*E_], g_w2[3*H_*E_];   // W^T split: [3][128 n][1024 k]

// ---------------------------------------------------------------------------
__device__ __forceinline__ uint32_t smem_u32(const void* p) {
    uint32_t a;
    asm("{ .reg .u64 t; cvta.to.shared.u64 t, %1; cvt.u32.u64 %0, t; }"
        : "=r"(a) : "l"(p));
    return a;
}

__device__ __forceinline__ void split2(float x, float y, uint32_t& hi, uint32_t& lo) {
    __half2 h = __floats2half2_rn(x, y);
    float2 f = __half22float2(h);
    __half2 l = __floats2half2_rn(x - f.x, y - f.y);
    hi = *(uint32_t*)&h; lo = *(uint32_t*)&l;
}

__device__ __forceinline__ void mma16(float* d, const uint32_t* a, const uint32_t* b) {
    asm volatile(
        "mma.sync.aligned.m16n8k16.row.col.f32.f16.f16.f32 "
        "{%0,%1,%2,%3}, {%4,%5,%6,%7}, {%8,%9}, {%0,%1,%2,%3};"
        : "+f"(d[0]), "+f"(d[1]), "+f"(d[2]), "+f"(d[3])
        : "r"(a[0]), "r"(a[1]), "r"(a[2]), "r"(a[3]), "r"(b[0]), "r"(b[1]));
}

__device__ __forceinline__ void ldsm4(uint32_t* r, uint32_t addr) {
    asm volatile("ldmatrix.sync.aligned.m8n8.x4.shared.b16 {%0,%1,%2,%3}, [%4];"
        : "=r"(r[0]), "=r"(r[1]), "=r"(r[2]), "=r"(r[3]) : "r"(addr));
}
__device__ __forceinline__ void ldsm4t(uint32_t* r, uint32_t addr) {
    asm volatile("ldmatrix.sync.aligned.m8n8.x4.trans.shared.b16 {%0,%1,%2,%3}, [%4];"
        : "=r"(r[0]), "=r"(r[1]), "=r"(r[2]), "=r"(r[3]) : "r"(addr));
}

// ---------------------------------------------------------------------------
// W -> W^T, split to fp16 halves.  grid (E/32, H/32, 3), 256 thr
// ---------------------------------------------------------------------------
__global__ void prep_w(const float* __restrict__ Wq,
                       const float* __restrict__ Wk,
                       const float* __restrict__ Wv)
{
    __shared__ float tile[32][33];
    const int sel = blockIdx.z;
    const float* __restrict__ W = (sel == 0) ? Wq : (sel == 1) ? Wk : Wv;
    const int k0 = blockIdx.x * 32, n0 = blockIdx.y * 32;
    const int tx = threadIdx.x & 31, ty = threadIdx.x >> 5;
#pragma unroll
    for (int i = 0; i < 4; i++)
        tile[ty + 8*i][tx] = W[(size_t)(k0 + ty + 8*i) * H_ + n0 + tx];
    __syncthreads();
    uint32_t* w1 = (uint32_t*)g_w1;
    uint32_t* w2 = (uint32_t*)g_w2;
#pragma unroll
    for (int r = 0; r < 2; r++) {
        int slot = r * 256 + threadIdx.x;
        int ni = slot >> 4, kp = slot & 15;
        float a = tile[2*kp][ni], b = tile[2*kp + 1][ni];
        uint32_t h, l;
        split2(a, b, h, l);
        size_t o = ((size_t)(sel * H_ + n0 + ni) * E_ + k0 + 2*kp) >> 1;
        w1[o] = h; w2[o] = l;
    }
}

// ---------------------------------------------------------------------------
// Projection: out = x @ W  via mma.sync fp16 split (3 products; 2 for V).
// CTA 64x128, 8 warps (2m x 4n), warp tile 32x32. K chunks of 32.
// ldmatrix fragments; double-buffered smem (1 sync per chunk); LDG prefetch.
// ---------------------------------------------------------------------------
#define PJS 40                       // halves per smem row
#define PJ_BUFH 15360                // halves per buffer
#define PJ_A1 0
#define PJ_A2 2560
#define PJ_B1 5120
#define PJ_B2 10240
#define PJ_SMEM (2 * PJ_BUFH * 2)    // 61440 B

__global__ __launch_bounds__(256, 2) void proj_tc(const float* __restrict__ x)
{
    extern __shared__ __half sh[];
    const uint32_t sb = smem_u32(sh);
    const int t    = threadIdx.x;
    const int wid  = t >> 5, lane = t & 31;
    const int wm   = wid >> 2, wn = wid & 3;
    const int g    = lane >> 2, tg = lane & 3;
    const int sel  = blockIdx.y;
    const int m0   = blockIdx.x * 64;

    const uint4* __restrict__ ws1 = (const uint4*)(g_w1 + (size_t)sel * H_ * E_);
    const uint4* __restrict__ ws2 = (const uint4*)(g_w2 + (size_t)sel * H_ * E_);
    float* outp = (sel == 0) ? g_q : (sel == 1) ? g_k : g_v;

    const int aoff = (lane & 15) * PJS + 8 * (lane >> 4);
    const int boff = ((lane & 7) + 8 * (lane >> 4)) * PJS + 8 * ((lane >> 3) & 1);

    float acc[2][4][4];
#pragma unroll
    for (int mi = 0; mi < 2; mi++)
#pragma unroll
        for (int ni = 0; ni < 4; ni++)
#pragma unroll
            for (int r = 0; r < 4; r++) acc[mi][ni][r] = 0.f;

    const int ac4 = t & 7;
    const int bc8 = t & 3;
    float4 fa[2];
    uint4  pw1[2], pw2[2];

    auto fetch = [&](int c) {
        const int k0 = c * 32;
#pragma unroll
        for (int p = 0; p < 2; p++) {
            int row = (p * 256 + t) >> 3;
            fa[p] = *(const float4*)&x[(size_t)(m0 + row) * E_ + k0 + ac4 * 4];
        }
#pragma unroll
        for (int p = 0; p < 2; p++) {
            int row = (p * 256 + t) >> 2;
            size_t off = ((size_t)row * E_ + k0) / 8 + bc8;
            pw1[p] = ws1[off];
            pw2[p] = ws2[off];
        }
    };
    auto store = [&](int buf) {
        __half* dst = sh + buf * PJ_BUFH;
#pragma unroll
        for (int p = 0; p < 2; p++) {
            int row = (p * 256 + t) >> 3;
            float4 v = fa[p];
            uint32_t h0, l0, h1, l1;
            split2(v.x, v.y, h0, l0);
            split2(v.z, v.w, h1, l1);
            int o = row * PJS + ac4 * 4;
            *(uint32_t*)&dst[PJ_A1 + o]     = h0;
            *(uint32_t*)&dst[PJ_A1 + o + 2] = h1;
            *(uint32_t*)&dst[PJ_A2 + o]     = l0;
            *(uint32_t*)&dst[PJ_A2 + o + 2] = l1;
        }
#pragma unroll
        for (int p = 0; p < 2; p++) {
            int row = (p * 256 + t) >> 2;
            int o = row * PJS + bc8 * 8;
            *(uint4*)&dst[PJ_B1 + o] = pw1[p];
            *(uint4*)&dst[PJ_B2 + o] = pw2[p];
        }
    };

    fetch(0);
    store(0);
    __syncthreads();

    for (int c = 0; c < 32; c++) {
        const int p = c & 1;
        if (c < 31) fetch(c + 1);

        const uint32_t bufb = sb + 2 * (p * PJ_BUFH);
        const uint32_t a1b = bufb + 2 * (PJ_A1 + wm * 32 * PJS + aoff);
        const uint32_t a2b = bufb + 2 * (PJ_A2 + wm * 32 * PJS + aoff);
        const uint32_t b1b = bufb + 2 * (PJ_B1 + wn * 32 * PJS + boff);
        const uint32_t b2b = bufb + 2 * (PJ_B2 + wn * 32 * PJS + boff);

#pragma unroll
        for (int s = 0; s < 2; s++) {
            uint32_t a1[2][4], a2[2][4];
#pragma unroll
            for (int mi = 0; mi < 2; mi++) {
                ldsm4(a1[mi], a1b + 2 * (mi * 16 * PJS + s * 16));
                ldsm4(a2[mi], a2b + 2 * (mi * 16 * PJS + s * 16));
            }
#pragma unroll
            for (int ng = 0; ng < 2; ng++) {
                uint32_t b1[4], b2[4];
                ldsm4(b1, b1b + 2 * (ng * 16 * PJS + s * 16));
                ldsm4(b2, b2b + 2 * (ng * 16 * PJS + s * 16));
#pragma unroll
                for (int mi = 0; mi < 2; mi++) {
                    mma16(acc[mi][2*ng],     a1[mi], b1);
                    mma16(acc[mi][2*ng + 1], a1[mi], b1 + 2);
                    mma16(acc[mi][2*ng],     a1[mi], b2);
                    mma16(acc[mi][2*ng + 1], a1[mi], b2 + 2);
                    if (sel < 2) {
                        mma16(acc[mi][2*ng],     a2[mi], b1);
                        mma16(acc[mi][2*ng + 1], a2[mi], b1 + 2);
                    }
                }
            }
        }
        if (c < 31) {
            store(p ^ 1);
            __syncthreads();
        }
    }

#pragma unroll
    for (int mi = 0; mi < 2; mi++) {
        int row = m0 + wm * 32 + mi * 16 + g;
#pragma unroll
        for (int ni = 0; ni < 4; ni++) {
            int col = wn * 32 + ni * 8 + tg * 2;
            *(float2*)&outp[(size_t)row * H_ + col] =
                make_float2(acc[mi][ni][0], acc[mi][ni][1]);
            *(float2*)&outp[(size_t)(row + 8) * H_ + col] =
                make_float2(acc[mi][ni][2], acc[mi][ni][3]);
        }
    }
}

// ---------------------------------------------------------------------------
// Flash attention, FA2 register dataflow. BQ=128, BK=64, 256 thr / 8 warps;
// each warp owns 16 rows x all 64 S-cols x all 128 O-cols.
// Softmax fully warp-local; P register-resident. Q in smem (frags re-loaded).
// K/V double-buffered with reg-prefetch; 1 syncthreads per tile.
// ---------------------------------------------------------------------------
#define QS1_ 0
#define QS2_ 17408
#define KB1_(b) (34816 + (b)*26112)
#define KB2_(b) (34816 + (b)*26112 + 8704)
#define VB_(b)  (34816 + (b)*26112 + 17408)
#define A_SMEM ((34816 + 2*26112) * 2)   // 174080 B

__global__ __launch_bounds__(256, 1) void attn_tc(float* __restrict__ out)
{
    extern __shared__ __half shh[];
    const uint32_t sb = smem_u32(shh);

    const int t    = threadIdx.x;
    const int wid  = t >> 5, lane = t & 31;
    const int g    = lane >> 2, tg = lane & 3;
    const int qt   = (int)gridDim.x - 1 - (int)blockIdx.x;
    const int b    = blockIdx.y;
    const size_t base = (size_t)b * (T_ * H_);
    const float scale = 45.25483399593904f;   // sqrt(2048)

    // ldmatrix lane offsets (half indices, stride 136)
    const int aoffQ = (lane & 15) * 136 + 8 * (lane >> 4);
    const int boffK = ((lane & 7) + 8 * (lane >> 4)) * 136 + 8 * ((lane >> 3) & 1);
    const int voffV = ((lane & 7) + 8 * ((lane >> 3) & 1)) * 136 + 8 * (lane >> 4);

    // ---- stage Q (128x128, scaled, split) into smem ----
#pragma unroll
    for (int p = 0; p < 16; p++) {
        int idx = p * 256 + t;
        int row = idx >> 5, c4 = idx & 31;
        float4 v = *(const float4*)&g_q[base + (size_t)(qt * 128 + row) * H_ + c4 * 4];
        v.x *= scale; v.y *= scale; v.z *= scale; v.w *= scale;
        uint32_t h0, l0, h1, l1;
        split2(v.x, v.y, h0, l0);
        split2(v.z, v.w, h1, l1);
        int o = row * 136 + c4 * 4;
        *(uint32_t*)&shh[QS1_ + o]     = h0;
        *(uint32_t*)&shh[QS1_ + o + 2] = h1;
        *(uint32_t*)&shh[QS2_ + o]     = l0;
        *(uint32_t*)&shh[QS2_ + o + 2] = l1;
    }

    float of[16][4];
#pragma unroll
    for (int nt = 0; nt < 16; nt++)
#pragma unroll
        for (int r = 0; r < 4; r++) of[nt][r] = 0.f;
    float mrun0 = -INFINITY, mrun1 = -INFINITY;
    float lrun0 = 0.f, lrun1 = 0.f;

    const int rowbase = qt * 128 + wid * 16;
    const int ntiles = 2 * qt + 2;
    const int lrow = t >> 5, lc4 = t & 31;   // K/V loader mapping

    float4 pk[8], pv[8];
    auto fetchKV = [&](int kt) {
#pragma unroll
        for (int pp = 0; pp < 8; pp++) {
            int row = pp * 8 + lrow;
            pk[pp] = *(const float4*)&g_k[base + (size_t)(kt * 64 + row) * H_ + lc4 * 4];
            pv[pp] = *(const float4*)&g_v[base + (size_t)(kt * 64 + row) * H_ + lc4 * 4];
        }
    };
    auto storeKV = [&](int buf) {
#pragma unroll
        for (int pp = 0; pp < 8; pp++) {
            int row = pp * 8 + lrow;
            int o = row * 136 + lc4 * 4;
            float4 v = pk[pp];
            uint32_t h0, l0, h1, l1;
            split2(v.x, v.y, h0, l0);
            split2(v.z, v.w, h1, l1);
            *(uint32_t*)&shh[KB1_(buf) + o]     = h0;
            *(uint32_t*)&shh[KB1_(buf) + o + 2] = h1;
            *(uint32_t*)&shh[KB2_(buf) + o]     = l0;
            *(uint32_t*)&shh[KB2_(buf) + o + 2] = l1;
            float4 w = pv[pp];
            __half2 va = __floats2half2_rn(w.x, w.y);
            __half2 vb = __floats2half2_rn(w.z, w.w);
            uint2 u = make_uint2(*(uint32_t*)&va, *(uint32_t*)&vb);
            *(uint2*)&shh[VB_(buf) + o] = u;
        }
    };

    fetchKV(0);
    storeKV(0);
    if (ntiles > 1) fetchKV(1);
    __syncthreads();

    for (int kt = 0; kt < ntiles; kt++) {
        const int p = kt & 1;
        if (kt + 1 < ntiles) {
            storeKV(p ^ 1);
            if (kt + 2 < ntiles) fetchKV(kt + 2);
        }

        // skip fully-masked warp-tiles (still hit the barrier below)
        if (kt * 64 <= rowbase + 15) {
            // ---- S = Q K^T (16 rows x 64 cols per warp), split-2, 3 products ----
            float sf[8][4];
#pragma unroll
            for (int ni = 0; ni < 8; ni++)
#pragma unroll
                for (int r = 0; r < 4; r++) sf[ni][r] = 0.f;

            const uint32_t qb1 = sb + 2 * (QS1_ + wid * 16 * 136 + aoffQ);
            const uint32_t qb2 = sb + 2 * (QS2_ + wid * 16 * 136 + aoffQ);
            const uint32_t kb1b = sb + 2 * (KB1_(p) + boffK);
            const uint32_t kb2b = sb + 2 * (KB2_(p) + boffK);
#pragma unroll
            for (int ks = 0; ks < 8; ks++) {
                uint32_t qa1[4], qa2[4];
                ldsm4(qa1, qb1 + 2 * (ks * 16));
                ldsm4(qa2, qb2 + 2 * (ks * 16));
#pragma unroll
                for (int ng = 0; ng < 4; ng++) {
                    uint32_t kb1[4], kb2[4];
                    ldsm4(kb1, kb1b + 2 * (ng * 16 * 136 + ks * 16));
                    ldsm4(kb2, kb2b + 2 * (ng * 16 * 136 + ks * 16));
                    mma16(sf[2*ng],     qa1, kb1);
                    mma16(sf[2*ng + 1], qa1, kb1 + 2);
                    mma16(sf[2*ng],     qa1, kb2);
                    mma16(sf[2*ng + 1], qa1, kb2 + 2);
                    mma16(sf[2*ng],     qa2, kb1);
                    mma16(sf[2*ng + 1], qa2, kb1 + 2);
                }
            }

            // ---- causal mask (partial warp-tiles only) ----
            if (kt * 64 + 63 > rowbase) {
                int grow0 = rowbase + g;
#pragma unroll
                for (int ni = 0; ni < 8; ni++) {
                    int gcol = kt * 64 + ni * 8 + tg * 2;
                    if (gcol     > grow0)     sf[ni][0] = -INFINITY;
                    if (gcol + 1 > grow0)     sf[ni][1] = -INFINITY;
                    if (gcol     > grow0 + 8) sf[ni][2] = -INFINITY;
                    if (gcol + 1 > grow0 + 8) sf[ni][3] = -INFINITY;
                }
            }

            // ---- warp-local online softmax ----
            float pm0 = -INFINITY, pm1 = -INFINITY;
#pragma unroll
            for (int ni = 0; ni < 8; ni++) {
                pm0 = fmaxf(pm0, fmaxf(sf[ni][0], sf[ni][1]));
                pm1 = fmaxf(pm1, fmaxf(sf[ni][2], sf[ni][3]));
            }
            pm0 = fmaxf(pm0, __shfl_xor_sync(0xffffffffu, pm0, 1));
            pm0 = fmaxf(pm0, __shfl_xor_sync(0xffffffffu, pm0, 2));
            pm1 = fmaxf(pm1, __shfl_xor_sync(0xffffffffu, pm1, 1));
            pm1 = fmaxf(pm1, __shfl_xor_sync(0xffffffffu, pm1, 2));

            float m0n = fmaxf(mrun0, pm0);
            float m1n = fmaxf(mrun1, pm1);
            float f0 = __expf(mrun0 - m0n);
            float f1 = __expf(mrun1 - m1n);
            mrun0 = m0n; mrun1 = m1n;

            float ps0 = 0.f, ps1 = 0.f;
            uint32_t pa[4][4];   // P A-fragments straight from S fragments
#pragma unroll
            for (int kk = 0; kk < 4; kk++) {
                float e00 = __expf(sf[2*kk][0] - m0n);
                float e01 = __expf(sf[2*kk][1] - m0n);
                float e02 = __expf(sf[2*kk][2] - m1n);
                float e03 = __expf(sf[2*kk][3] - m1n);
                float e10 = __expf(sf[2*kk+1][0] - m0n);
                float e11 = __expf(sf[2*kk+1][1] - m0n);
                float e12 = __expf(sf[2*kk+1][2] - m1n);
                float e13 = __expf(sf[2*kk+1][3] - m1n);
                ps0 += e00 + e01 + e10 + e11;
                ps1 += e02 + e03 + e12 + e13;
                __half2 h;
                h = __floats2half2_rn(e00, e01); pa[kk][0] = *(uint32_t*)&h;
                h = __floats2half2_rn(e02, e03); pa[kk][1] = *(uint32_t*)&h;
                h = __floats2half2_rn(e10, e11); pa[kk][2] = *(uint32_t*)&h;
                h = __floats2half2_rn(e12, e13); pa[kk][3] = *(uint32_t*)&h;
            }
            ps0 += __shfl_xor_sync(0xffffffffu, ps0, 1);
            ps0 += __shfl_xor_sync(0xffffffffu, ps0, 2);
            ps1 += __shfl_xor_sync(0xffffffffu, ps1, 1);
            ps1 += __shfl_xor_sync(0xffffffffu, ps1, 2);
            lrun0 = lrun0 * f0 + ps0;
            lrun1 = lrun1 * f1 + ps1;

            // ---- rescale O ----
#pragma unroll
            for (int nt = 0; nt < 16; nt++) {
                of[nt][0] *= f0; of[nt][1] *= f0;
                of[nt][2] *= f1; of[nt][3] *= f1;
            }

            // ---- O += P V  (P in registers) ----
            const uint32_t vbb = sb + 2 * (VB_(p) + voffV);
#pragma unroll
            for (int kk = 0; kk < 4; kk++) {
#pragma unroll
                for (int ng = 0; ng < 8; ng++) {
                    uint32_t vb[4];
                    ldsm4t(vb, vbb + 2 * (kk * 16 * 136 + ng * 16));
                    mma16(of[2*ng],     pa[kk], vb);
                    mma16(of[2*ng + 1], pa[kk], vb + 2);
                }
            }
        }

        __syncthreads();   // tile p consumed; buf p free; buf p^1 stores visible
    }

    // ---- epilogue ----
    float inv0 = 1.f / lrun0;
    float inv1 = 1.f / lrun1;
    int grow = rowbase + g;
#pragma unroll
    for (int nt = 0; nt < 16; nt++) {
        int col = nt * 8 + tg * 2;
        *(float2*)&out[base + (size_t)grow * H_ + col] =
            make_float2(of[nt][0] * inv0, of[nt][1] * inv0);
        *(float2*)&out[base + (size_t)(grow + 8) * H_ + col] =
            make_float2(of[nt][2] * inv1, of[nt][3] * inv1);
    }
}

// ---------------------------------------------------------------------------
extern "C" void kernel_launch(void* const* d_in, const int* in_sizes, int n_in,
                              void* d_out, int out_size)
{
    const float* x  = (const float*)d_in[0];
    const float* Wq = (const float*)d_in[1];
    const float* Wk = (const float*)d_in[2];
    const float* Wv = (const float*)d_in[3];
    float* out = (float*)d_out;

    prep_w<<<dim3(E_/32, H_/32, 3), 256>>>(Wq, Wk, Wv);

    cudaFuncSetAttribute(proj_tc,
                         cudaFuncAttributeMaxDynamicSharedMemorySize, PJ_SMEM);
    proj_tc<<<dim3(BT_/64, 3), 256, PJ_SMEM>>>(x);

    cudaFuncSetAttribute(attn_tc,
                         cudaFuncAttributeMaxDynamicSharedMemorySize, A_SMEM);
    attn_tc<<<dim3(T_/128, B_), 256, A_SMEM>>>(out);
}